// round 1
// baseline (speedup 1.0000x reference)
#include <cuda_runtime.h>
#include <math.h>

#define BB 4
#define CC 64
#define OO 64
#define HH 128
#define WW 128
#define HW (HH*WW)
#define KT 9

// Scratch: transposed weights [k][c][o]
__device__ float g_wt[KT*CC*OO];

__global__ void prep_wt_kernel(const float* __restrict__ w) {
    int i = blockIdx.x * 256 + threadIdx.x;
    if (i >= KT*CC*OO) return;
    int o = i % OO;
    int c = (i / OO) % CC;
    int k = i / (OO*CC);
    // w layout: [O][C][3][3] = [O][C][9]
    g_wt[i] = w[(o*CC + c)*KT + k];
}

__global__ __launch_bounds__(128) void deform_main_kernel(
    const float* __restrict__ x,
    const float* __restrict__ off_w,
    const float* __restrict__ off_b,
    const float* __restrict__ bn_gamma,
    const float* __restrict__ bn_beta,
    const float* __restrict__ bn_mean,
    const float* __restrict__ bn_var,
    const float* __restrict__ dconv_b,
    float* __restrict__ out)
{
    __shared__ float s_offw[CC*20];   // transposed+padded: [c][j], j<18, stride 20 (float4-aligned)
    __shared__ float s_w[CC*OO];      // per-k weight slice [c][o]
    __shared__ float s_oscale[18];
    __shared__ float s_obias[18];

    const int tid = threadIdx.x;

    // Load off_w transposed: off_w is [18][C]
    for (int i = tid; i < 18*CC; i += 128) {
        int j = i / CC;
        int c = i % CC;
        s_offw[c*20 + j] = off_w[i];
    }
    if (tid < 18) {
        float sc = bn_gamma[tid] * rsqrtf(bn_var[tid] + 1e-5f);
        s_oscale[tid] = sc;
        s_obias[tid]  = (off_b[tid] - bn_mean[tid]) * sc + bn_beta[tid];
    }
    __syncthreads();

    const int pix = blockIdx.x * 128 + tid;     // grid = 512 blocks -> exact
    const int b  = pix / HW;
    const int p  = pix % HW;
    const int h  = p / WW;
    const int w_ = p % WW;
    const float* xb = x + (size_t)b * CC * HW;

    // ---- Offset branch: pre[j] = sum_c x[c]*off_w[j,c] ----
    float a18[18];
    #pragma unroll
    for (int j = 0; j < 18; j++) a18[j] = 0.f;

    #pragma unroll 4
    for (int c = 0; c < CC; c++) {
        float xv = xb[c*HW + p];
        const float* r = s_offw + c*20;
        #pragma unroll
        for (int j = 0; j < 18; j++) a18[j] += xv * r[j];
    }

    // BN(folded) + tanh * 0.75; layout [9][2] = (dy,dx) per tap
    float offy[9], offx[9];
    #pragma unroll
    for (int k = 0; k < 9; k++) {
        float vy = a18[2*k]   * s_oscale[2*k]   + s_obias[2*k];
        float vx = a18[2*k+1] * s_oscale[2*k+1] + s_obias[2*k+1];
        offy[k] = tanhf(vy) * 0.75f;
        offx[k] = tanhf(vx) * 0.75f;
    }

    // ---- Deform conv ----
    float acc[OO];
    #pragma unroll
    for (int o = 0; o < OO; o++) acc[o] = 0.f;

    for (int k = 0; k < 9; k++) {
        __syncthreads();
        {
            const float4* src = (const float4*)(g_wt + k*CC*OO);
            float4* dst = (float4*)s_w;
            #pragma unroll
            for (int i = tid; i < CC*OO/4; i += 128) dst[i] = src[i];
        }
        __syncthreads();

        const int kyi = k / 3 - 1;
        const int kxi = k % 3 - 1;
        float py = (float)(h + kyi) + offy[k];
        float px = (float)(w_ + kxi) + offx[k];
        float fy = floorf(py), fx = floorf(px);
        float wy = py - fy,    wx = px - fx;
        int y0 = (int)fy, x0 = (int)fx;
        int y1 = y0 + 1,  x1 = x0 + 1;

        float vy0 = (y0 >= 0 && y0 < HH) ? 1.f : 0.f;
        float vy1 = (y1 >= 0 && y1 < HH) ? 1.f : 0.f;
        float vx0 = (x0 >= 0 && x0 < WW) ? 1.f : 0.f;
        float vx1 = (x1 >= 0 && x1 < WW) ? 1.f : 0.f;

        float w00 = (1.f - wy) * (1.f - wx) * vy0 * vx0;
        float w01 = (1.f - wy) * wx         * vy0 * vx1;
        float w10 = wy         * (1.f - wx) * vy1 * vx0;
        float w11 = wy         * wx         * vy1 * vx1;

        int yc0 = min(max(y0, 0), HH - 1);
        int yc1 = min(max(y1, 0), HH - 1);
        int xc0 = min(max(x0, 0), WW - 1);
        int xc1 = min(max(x1, 0), WW - 1);
        int i00 = yc0*WW + xc0;
        int i01 = yc0*WW + xc1;
        int i10 = yc1*WW + xc0;
        int i11 = yc1*WW + xc1;

        #pragma unroll 4
        for (int c = 0; c < CC; c++) {
            const float* xc = xb + c*HW;
            float s = w00*xc[i00] + w01*xc[i01] + w10*xc[i10] + w11*xc[i11];
            const float* wr = s_w + c*OO;
            #pragma unroll
            for (int o = 0; o < OO; o++) acc[o] += s * wr[o];
        }
    }

    // ---- Epilogue ----
    float* ob = out + (size_t)b * OO * HW + p;
    #pragma unroll
    for (int o = 0; o < OO; o++) {
        ob[o*HW] = acc[o] + dconv_b[o];
    }
}

extern "C" void kernel_launch(void* const* d_in, const int* in_sizes, int n_in,
                              void* d_out, int out_size) {
    const float* x        = (const float*)d_in[0];
    const float* off_w    = (const float*)d_in[1];
    const float* off_b    = (const float*)d_in[2];
    const float* bn_gamma = (const float*)d_in[3];
    const float* bn_beta  = (const float*)d_in[4];
    const float* bn_mean  = (const float*)d_in[5];
    const float* bn_var   = (const float*)d_in[6];
    const float* dconv_w  = (const float*)d_in[7];
    const float* dconv_b  = (const float*)d_in[8];
    float* out = (float*)d_out;

    prep_wt_kernel<<<(KT*CC*OO + 255)/256, 256>>>(dconv_w);
    deform_main_kernel<<<(BB*HW)/128, 128>>>(
        x, off_w, off_b, bn_gamma, bn_beta, bn_mean, bn_var, dconv_b, out);
}

// round 2
// speedup vs baseline: 1.1510x; 1.1510x over previous
#include <cuda_runtime.h>
#include <math.h>

#define BB 4
#define CC 64
#define OO 64
#define HH 128
#define WW 128
#define HW (HH*WW)
#define KT 9

// ---- smem layout (in floats) ----
#define OFF_SAMP 0          // [64][128]            8192
#define OFF_W    8192       // [64][64]             4096
#define OFF_OFFJ 12288      // [18][128]            2304
#define OFF_CW   14592      // float4[128]           512
#define OFF_CI   15104      // int4[128]             512
#define OFF_OFFW 15616      // [64][20]             1280
#define OFF_SC   16896      // [18]
#define OFF_SB   16914      // [18]
#define OFF_BIAS 16932      // [64]
#define SMEM_FLOATS 16996
#define SMEM_BYTES (SMEM_FLOATS*4)

// Scratch: transposed weights [k][c][o]
__device__ float g_wt[KT*CC*OO];

__global__ void prep_wt_kernel(const float* __restrict__ w) {
    int i = blockIdx.x * 256 + threadIdx.x;
    if (i >= KT*CC*OO) return;
    int o = i % OO;
    int c = (i / OO) % CC;
    int k = i / (OO*CC);
    g_wt[i] = w[(o*CC + c)*KT + k];
}

__device__ __forceinline__ unsigned long long pack2(float a, float b) {
    unsigned long long r;
    asm("mov.b64 %0, {%1, %2};" : "=l"(r) : "f"(a), "f"(b));
    return r;
}
__device__ __forceinline__ unsigned long long dup2(float a) {
    unsigned long long r;
    asm("mov.b64 %0, {%1, %1};" : "=l"(r) : "f"(a));
    return r;
}
__device__ __forceinline__ void fma2(unsigned long long& d, unsigned long long a, unsigned long long b) {
    asm("fma.rn.f32x2 %0, %1, %2, %0;" : "+l"(d) : "l"(a), "l"(b));
}
__device__ __forceinline__ void unpack2(unsigned long long v, float& lo, float& hi) {
    asm("mov.b64 {%0, %1}, %2;" : "=f"(lo), "=f"(hi) : "l"(v));
}

__global__ __launch_bounds__(256) void deform_main_kernel(
    const float* __restrict__ x,
    const float* __restrict__ off_w,
    const float* __restrict__ off_b,
    const float* __restrict__ bn_gamma,
    const float* __restrict__ bn_beta,
    const float* __restrict__ bn_mean,
    const float* __restrict__ bn_var,
    const float* __restrict__ dconv_b,
    float* __restrict__ out)
{
    extern __shared__ float smem[];
    float* s_samp = smem + OFF_SAMP;   // [c][pix]
    float* s_w    = smem + OFF_W;      // [c][o]
    float* s_offj = smem + OFF_OFFJ;   // [j][pix]
    float4* s_cw  = (float4*)(smem + OFF_CW);
    int4*   s_ci  = (int4*)(smem + OFF_CI);
    float* s_offw = smem + OFF_OFFW;   // [c][20]
    float* s_sc   = smem + OFF_SC;
    float* s_sb   = smem + OFF_SB;
    float* s_bias = smem + OFF_BIAS;

    const int tid  = threadIdx.x;
    const int lane = tid & 31;
    const int wrp  = tid >> 5;          // 8 warps -> o-tile
    const int blk  = blockIdx.x;        // 512 = BB*HH
    const int b    = blk >> 7;          // /128
    const int h    = blk & 127;
    const float* xb = x + (size_t)b * CC * HW;

    // ---- Prologue: stage constants ----
    for (int i = tid; i < 18*CC; i += 256) {
        int j = i / CC, c = i % CC;
        s_offw[c*20 + j] = off_w[i];
    }
    if (tid < 18) {
        float sc = bn_gamma[tid] * rsqrtf(bn_var[tid] + 1e-5f);
        s_sc[tid] = sc;
        s_sb[tid] = (off_b[tid] - bn_mean[tid]) * sc + bn_beta[tid];
    }
    if (tid < OO) s_bias[tid] = dconv_b[tid];
    __syncthreads();

    // ---- Offset branch: 2 threads per pixel, 9 j's each ----
    {
        const int pix  = tid & 127;
        const int jb   = (tid >> 7) * 9;     // 0 or 9
        const int p    = h*WW + pix;
        float a9[9];
        #pragma unroll
        for (int j = 0; j < 9; j++) a9[j] = 0.f;
        #pragma unroll 4
        for (int c = 0; c < CC; c++) {
            float xv = xb[c*HW + p];
            const float* r = s_offw + c*20 + jb;
            #pragma unroll
            for (int j = 0; j < 9; j++) a9[j] += xv * r[j];
        }
        #pragma unroll
        for (int jj = 0; jj < 9; jj++) {
            int j = jb + jj;
            float v = a9[jj] * s_sc[j] + s_sb[j];
            s_offj[j*128 + pix] = tanhf(v) * 0.75f;
        }
    }

    // ---- Accumulators: 4 pix x 8 o as 16 f32x2 pairs (pair over o) ----
    unsigned long long accp[16];
    #pragma unroll
    for (int i = 0; i < 16; i++) accp[i] = 0ULL;

    for (int k = 0; k < KT; k++) {
        __syncthreads();   // prev iter done with s_samp / s_w

        // corner precompute (one thread per pixel)
        if (tid < 128) {
            const int pix = tid;
            const int kyi = k / 3 - 1;
            const int kxi = k % 3 - 1;
            float py = (float)(h + kyi) + s_offj[(2*k)*128 + pix];
            float px = (float)(pix + kxi) + s_offj[(2*k+1)*128 + pix];
            float fy = floorf(py), fx = floorf(px);
            float wy = py - fy,    wx = px - fx;
            int y0 = (int)fy, x0 = (int)fx;
            int y1 = y0 + 1,  x1 = x0 + 1;
            float vy0 = (y0 >= 0 && y0 < HH) ? 1.f : 0.f;
            float vy1 = (y1 >= 0 && y1 < HH) ? 1.f : 0.f;
            float vx0 = (x0 >= 0 && x0 < WW) ? 1.f : 0.f;
            float vx1 = (x1 >= 0 && x1 < WW) ? 1.f : 0.f;
            float4 wv;
            wv.x = (1.f - wy) * (1.f - wx) * vy0 * vx0;
            wv.y = (1.f - wy) * wx         * vy0 * vx1;
            wv.z = wy         * (1.f - wx) * vy1 * vx0;
            wv.w = wy         * wx         * vy1 * vx1;
            int yc0 = min(max(y0, 0), HH-1), yc1 = min(max(y1, 0), HH-1);
            int xc0 = min(max(x0, 0), WW-1), xc1 = min(max(x1, 0), WW-1);
            int4 iv;
            iv.x = yc0*WW + xc0; iv.y = yc0*WW + xc1;
            iv.z = yc1*WW + xc0; iv.w = yc1*WW + xc1;
            s_cw[pix] = wv;
            s_ci[pix] = iv;
        }
        // stage weight slice k: 4096 floats, float4 strided
        {
            const float4* src = (const float4*)(g_wt + k*CC*OO);
            float4* dst = (float4*)s_w;
            #pragma unroll
            for (int i = tid; i < CC*OO/4; i += 256) dst[i] = src[i];
        }
        __syncthreads();   // corners + weights visible

        // gather: 8192 (c,pix) entries, 32 per thread
        #pragma unroll 4
        for (int i = 0; i < 32; i++) {
            int e   = tid + (i << 8);
            int c   = e >> 7;
            int pix = e & 127;
            float4 wv = s_cw[pix];
            int4   iv = s_ci[pix];
            const float* xc = xb + c*HW;
            float s = wv.x*xc[iv.x] + wv.y*xc[iv.y] + wv.z*xc[iv.z] + wv.w*xc[iv.w];
            s_samp[c*128 + pix] = s;
        }
        __syncthreads();   // samp ready

        // ---- contraction: per c, 3 LDS.128 + 16 fma.f32x2 ----
        const float* samp_base = s_samp + 4*lane;
        const float* w_base    = s_w + 8*wrp;
        #pragma unroll 4
        for (int c = 0; c < CC; c++) {
            float4 s4 = *(const float4*)(samp_base + c*128);
            ulonglong2 wa = *(const ulonglong2*)(w_base + c*64);       // o0..3
            ulonglong2 wb = *(const ulonglong2*)(w_base + c*64 + 4);   // o4..7
            unsigned long long sp0 = dup2(s4.x);
            unsigned long long sp1 = dup2(s4.y);
            unsigned long long sp2 = dup2(s4.z);
            unsigned long long sp3 = dup2(s4.w);
            fma2(accp[ 0], sp0, wa.x); fma2(accp[ 1], sp0, wa.y);
            fma2(accp[ 2], sp0, wb.x); fma2(accp[ 3], sp0, wb.y);
            fma2(accp[ 4], sp1, wa.x); fma2(accp[ 5], sp1, wa.y);
            fma2(accp[ 6], sp1, wb.x); fma2(accp[ 7], sp1, wb.y);
            fma2(accp[ 8], sp2, wa.x); fma2(accp[ 9], sp2, wa.y);
            fma2(accp[10], sp2, wb.x); fma2(accp[11], sp2, wb.y);
            fma2(accp[12], sp3, wa.x); fma2(accp[13], sp3, wa.y);
            fma2(accp[14], sp3, wb.x); fma2(accp[15], sp3, wb.y);
        }
    }

    // ---- Epilogue: transpose pairs -> float4 over pixels, STG.128 ----
    const int obase = 8*wrp;
    const int pbase = h*WW + 4*lane;
    #pragma unroll
    for (int j = 0; j < 4; j++) {
        float lo[4], hi[4];
        #pragma unroll
        for (int q = 0; q < 4; q++) unpack2(accp[q*4 + j], lo[q], hi[q]);
        int o0 = obase + 2*j;
        int o1 = o0 + 1;
        float b0 = s_bias[o0], b1 = s_bias[o1];
        float4 v0 = make_float4(lo[0]+b0, lo[1]+b0, lo[2]+b0, lo[3]+b0);
        float4 v1 = make_float4(hi[0]+b1, hi[1]+b1, hi[2]+b1, hi[3]+b1);
        *(float4*)(out + ((size_t)(b*OO + o0))*HW + pbase) = v0;
        *(float4*)(out + ((size_t)(b*OO + o1))*HW + pbase) = v1;
    }
}

extern "C" void kernel_launch(void* const* d_in, const int* in_sizes, int n_in,
                              void* d_out, int out_size) {
    const float* x        = (const float*)d_in[0];
    const float* off_w    = (const float*)d_in[1];
    const float* off_b    = (const float*)d_in[2];
    const float* bn_gamma = (const float*)d_in[3];
    const float* bn_beta  = (const float*)d_in[4];
    const float* bn_mean  = (const float*)d_in[5];
    const float* bn_var   = (const float*)d_in[6];
    const float* dconv_w  = (const float*)d_in[7];
    const float* dconv_b  = (const float*)d_in[8];
    float* out = (float*)d_out;

    cudaFuncSetAttribute(deform_main_kernel,
                         cudaFuncAttributeMaxDynamicSharedMemorySize, SMEM_BYTES);

    prep_wt_kernel<<<(KT*CC*OO + 255)/256, 256>>>(dconv_w);
    deform_main_kernel<<<BB*HH, 256, SMEM_BYTES>>>(
        x, off_w, off_b, bn_gamma, bn_beta, bn_mean, bn_var, dconv_b, out);
}

// round 3
// speedup vs baseline: 1.4475x; 1.2576x over previous
#include <cuda_runtime.h>
#include <math.h>

#define BB 4
#define CC 64
#define OO 64
#define HH 128
#define WW 128
#define HW (HH*WW)
#define KT 9

// ---- smem layout (float offsets) ----
#define S_SAMP0 0        // [64][128]
#define S_SAMP1 8192     // [64][128]
#define S_W     16384    // [64][64]
#define S_OFFJ  20480    // [18][128]
#define S_OFFW  22784    // [64][20]
#define S_SC    24064
#define S_SB    24082
#define S_BIAS  24100
#define SMEM_FLOATS 24164
#define SMEM_BYTES (SMEM_FLOATS*4)

// transposed weights [k][c][o]
__device__ float g_wt[KT*CC*OO];

__global__ void prep_wt_kernel(const float* __restrict__ w) {
    int i = blockIdx.x * 256 + threadIdx.x;
    if (i >= KT*CC*OO) return;
    int o = i % OO;
    int c = (i / OO) % CC;
    int k = i / (OO*CC);
    g_wt[i] = w[(o*CC + c)*KT + k];
}

__device__ __forceinline__ unsigned long long dup2(float a) {
    unsigned long long r;
    asm("mov.b64 %0, {%1, %1};" : "=l"(r) : "f"(a));
    return r;
}
__device__ __forceinline__ void fma2(unsigned long long& d, unsigned long long a, unsigned long long b) {
    asm("fma.rn.f32x2 %0, %1, %2, %0;" : "+l"(d) : "l"(a), "l"(b));
}
__device__ __forceinline__ void unpack2(unsigned long long v, float& lo, float& hi) {
    asm("mov.b64 {%0, %1}, %2;" : "=f"(lo), "=f"(hi) : "l"(v));
}

__global__ __launch_bounds__(256, 2) void deform_main_kernel(
    const float* __restrict__ x,
    const float* __restrict__ off_w,
    const float* __restrict__ off_b,
    const float* __restrict__ bn_gamma,
    const float* __restrict__ bn_beta,
    const float* __restrict__ bn_mean,
    const float* __restrict__ bn_var,
    const float* __restrict__ dconv_b,
    float* __restrict__ out)
{
    extern __shared__ float smem[];

    const int tid  = threadIdx.x;
    const int lane = tid & 31;
    const int wrp  = tid >> 5;
    const int b    = blockIdx.x >> 7;
    const int h    = blockIdx.x & 127;
    const int pix  = tid & 127;
    const int half = tid >> 7;        // 0/1: which c-parity this thread gathers
    const float* xb = x + (size_t)b * CC * HW;

    // ---- Prologue ----
    for (int i = tid; i < 18*CC; i += 256) {
        int j = i / CC, c = i % CC;
        smem[S_OFFW + c*20 + j] = off_w[i];
    }
    if (tid < 18) {
        float sc = bn_gamma[tid] * rsqrtf(bn_var[tid] + 1e-5f);
        smem[S_SC + tid] = sc;
        smem[S_SB + tid] = (off_b[tid] - bn_mean[tid]) * sc + bn_beta[tid];
    }
    if (tid < OO) smem[S_BIAS + tid] = dconv_b[tid];
    __syncthreads();

    // ---- Offset branch: 2 threads per pixel, 9 j's each ----
    {
        const int jb = half * 9;
        const int p  = h*WW + pix;
        float a9[9];
        #pragma unroll
        for (int j = 0; j < 9; j++) a9[j] = 0.f;
        #pragma unroll 4
        for (int c = 0; c < CC; c++) {
            float xv = __ldg(xb + c*HW + p);
            const float* r = smem + S_OFFW + c*20 + jb;
            #pragma unroll
            for (int j = 0; j < 9; j++) a9[j] += xv * r[j];
        }
        #pragma unroll
        for (int jj = 0; jj < 9; jj++) {
            int j = jb + jj;
            float v = a9[jj] * smem[S_SC + j] + smem[S_SB + j];
            smem[S_OFFJ + j*128 + pix] = tanhf(v) * 0.75f;
        }
    }
    __syncthreads();

    // corner computation for tap k at this thread's pixel
    auto corners = [&](int k, float4& wv, int4& iv) {
        const int kyi = k / 3 - 1;
        const int kxi = k % 3 - 1;
        float py = (float)(h + kyi)   + smem[S_OFFJ + (2*k)*128 + pix];
        float px = (float)(pix + kxi) + smem[S_OFFJ + (2*k+1)*128 + pix];
        float fy = floorf(py), fx = floorf(px);
        float wy = py - fy,    wx = px - fx;
        int y0 = (int)fy, x0 = (int)fx;
        int y1 = y0 + 1,  x1 = x0 + 1;
        float vy0 = (y0 >= 0 && y0 < HH) ? 1.f : 0.f;
        float vy1 = (y1 >= 0 && y1 < HH) ? 1.f : 0.f;
        float vx0 = (x0 >= 0 && x0 < WW) ? 1.f : 0.f;
        float vx1 = (x1 >= 0 && x1 < WW) ? 1.f : 0.f;
        wv.x = (1.f - wy) * (1.f - wx) * vy0 * vx0;
        wv.y = (1.f - wy) * wx         * vy0 * vx1;
        wv.z = wy         * (1.f - wx) * vy1 * vx0;
        wv.w = wy         * wx         * vy1 * vx1;
        int yc0 = min(max(y0, 0), HH-1), yc1 = min(max(y1, 0), HH-1);
        int xc0 = min(max(x0, 0), WW-1), xc1 = min(max(x1, 0), WW-1);
        iv.x = yc0*WW + xc0; iv.y = yc0*WW + xc1;
        iv.z = yc1*WW + xc0; iv.w = yc1*WW + xc1;
    };

    // ---- Pre-loop: gather tap 0 -> SAMP0, stage weights tap 0 -> S_W ----
    {
        float4 wv; int4 iv;
        corners(0, wv, iv);
        const float4* wsrc = (const float4*)g_wt;
        float4* wdst = (float4*)(smem + S_W);
        #pragma unroll
        for (int q = 0; q < 4; q++) wdst[tid + 256*q] = wsrc[tid + 256*q];
        #pragma unroll 4
        for (int i = 0; i < 32; i++) {
            int c = half + 2*i;
            const float* bp = xb + c*HW;
            float v00 = __ldg(bp + iv.x), v01 = __ldg(bp + iv.y);
            float v10 = __ldg(bp + iv.z), v11 = __ldg(bp + iv.w);
            smem[S_SAMP0 + c*128 + pix] = wv.x*v00 + wv.y*v01 + wv.z*v10 + wv.w*v11;
        }
    }
    __syncthreads();

    // ---- Main pipelined loop ----
    unsigned long long accp[16];
    #pragma unroll
    for (int i = 0; i < 16; i++) accp[i] = 0ULL;

    #pragma unroll 1
    for (int k = 0; k < KT; k++) {
        const float* s_cur = smem + ((k & 1) ? S_SAMP1 : S_SAMP0);
        float*       s_nxt = smem + ((k & 1) ? S_SAMP0 : S_SAMP1);
        const bool pf = (k < KT-1);

        float4 wv; int4 iv;
        float4 wst[4];
        if (pf) {
            corners(k+1, wv, iv);
            const float4* wsrc = (const float4*)(g_wt + (k+1)*CC*OO);
            #pragma unroll
            for (int q = 0; q < 4; q++) wst[q] = __ldg(wsrc + tid + 256*q);
        }

        const float* samp_base = s_cur + 4*lane;
        const float* w_base    = smem + S_W + 8*wrp;

        #pragma unroll
        for (int cc = 0; cc < 8; cc++) {
            float v[16];
            if (pf) {
                #pragma unroll
                for (int e = 0; e < 4; e++) {
                    int c = half + 2*(cc*4 + e);
                    const float* bp = xb + c*HW;
                    v[4*e+0] = __ldg(bp + iv.x);
                    v[4*e+1] = __ldg(bp + iv.y);
                    v[4*e+2] = __ldg(bp + iv.z);
                    v[4*e+3] = __ldg(bp + iv.w);
                }
            }
            #pragma unroll
            for (int u = 0; u < 8; u++) {
                int c = cc*8 + u;
                float4 s4 = *(const float4*)(samp_base + c*128);
                ulonglong2 wa = *(const ulonglong2*)(w_base + c*64);
                ulonglong2 wb = *(const ulonglong2*)(w_base + c*64 + 4);
                unsigned long long sp0 = dup2(s4.x);
                unsigned long long sp1 = dup2(s4.y);
                unsigned long long sp2 = dup2(s4.z);
                unsigned long long sp3 = dup2(s4.w);
                fma2(accp[ 0], sp0, wa.x); fma2(accp[ 1], sp0, wa.y);
                fma2(accp[ 2], sp0, wb.x); fma2(accp[ 3], sp0, wb.y);
                fma2(accp[ 4], sp1, wa.x); fma2(accp[ 5], sp1, wa.y);
                fma2(accp[ 6], sp1, wb.x); fma2(accp[ 7], sp1, wb.y);
                fma2(accp[ 8], sp2, wa.x); fma2(accp[ 9], sp2, wa.y);
                fma2(accp[10], sp2, wb.x); fma2(accp[11], sp2, wb.y);
                fma2(accp[12], sp3, wa.x); fma2(accp[13], sp3, wa.y);
                fma2(accp[14], sp3, wb.x); fma2(accp[15], sp3, wb.y);
            }
            if (pf) {
                #pragma unroll
                for (int e = 0; e < 4; e++) {
                    int c = half + 2*(cc*4 + e);
                    s_nxt[c*128 + pix] =
                        wv.x*v[4*e+0] + wv.y*v[4*e+1] + wv.z*v[4*e+2] + wv.w*v[4*e+3];
                }
            }
        }

        __syncthreads();   // next samp complete; weights consumed
        if (pf) {
            float4* wdst = (float4*)(smem + S_W);
            #pragma unroll
            for (int q = 0; q < 4; q++) wdst[tid + 256*q] = wst[q];
            __syncthreads();
        }
    }

    // ---- Epilogue ----
    const int obase = 8*wrp;
    const int pbase = h*WW + 4*lane;
    #pragma unroll
    for (int j = 0; j < 4; j++) {
        float lo[4], hi[4];
        #pragma unroll
        for (int q = 0; q < 4; q++) unpack2(accp[q*4 + j], lo[q], hi[q]);
        int o0 = obase + 2*j;
        int o1 = o0 + 1;
        float b0 = smem[S_BIAS + o0], b1 = smem[S_BIAS + o1];
        float4 v0 = make_float4(lo[0]+b0, lo[1]+b0, lo[2]+b0, lo[3]+b0);
        float4 v1 = make_float4(hi[0]+b1, hi[1]+b1, hi[2]+b1, hi[3]+b1);
        *(float4*)(out + ((size_t)(b*OO + o0))*HW + pbase) = v0;
        *(float4*)(out + ((size_t)(b*OO + o1))*HW + pbase) = v1;
    }
}

extern "C" void kernel_launch(void* const* d_in, const int* in_sizes, int n_in,
                              void* d_out, int out_size) {
    const float* x        = (const float*)d_in[0];
    const float* off_w    = (const float*)d_in[1];
    const float* off_b    = (const float*)d_in[2];
    const float* bn_gamma = (const float*)d_in[3];
    const float* bn_beta  = (const float*)d_in[4];
    const float* bn_mean  = (const float*)d_in[5];
    const float* bn_var   = (const float*)d_in[6];
    const float* dconv_w  = (const float*)d_in[7];
    const float* dconv_b  = (const float*)d_in[8];
    float* out = (float*)d_out;

    cudaFuncSetAttribute(deform_main_kernel,
                         cudaFuncAttributeMaxDynamicSharedMemorySize, SMEM_BYTES);

    prep_wt_kernel<<<(KT*CC*OO + 255)/256, 256>>>(dconv_w);
    deform_main_kernel<<<BB*HH, 256, SMEM_BYTES>>>(
        x, off_w, off_b, bn_gamma, bn_beta, bn_mean, bn_var, dconv_b, out);
}